// round 5
// baseline (speedup 1.0000x reference)
#include <cuda_runtime.h>
#include <cuda_bf16.h>
#include <cstdint>

namespace {
constexpr int Tt  = 2048;
constexpr int Ee  = 1024;
constexpr int HD  = 64;
constexpr int BM  = 128;            // q rows per CTA
constexpr int BN  = 64;             // k tile
constexpr int NT  = 256;            // 8 warps
constexpr int NHtot = 64;
constexpr float SCALE = 0.125f;
constexpr int PLANE  = 8192;        // 64-token plane (128B rows, swizzled)
constexpr int QPLANE = 16384;       // 128-token plane
constexpr int STAGE  = 2 * PLANE;   // hi+lo K/V stage (16 KB)
constexpr int OFF_Q  = 0;           // Q hi/lo: 32 KB persistent
constexpr int OFF_S  = 2 * QPLANE;  // 4 stages x 16 KB
constexpr int SMEM_BYTES = OFF_S + 4 * STAGE;   // 98304
}

// preconverted per-head bf16 hi/lo planes: [nh][t][d]
__device__ __align__(128) __nv_bfloat16 gQh[(size_t)NHtot * Tt * HD];
__device__ __align__(128) __nv_bfloat16 gQl[(size_t)NHtot * Tt * HD];
__device__ __align__(128) __nv_bfloat16 gKh[(size_t)NHtot * Tt * HD];
__device__ __align__(128) __nv_bfloat16 gKl[(size_t)NHtot * Tt * HD];
__device__ __align__(128) __nv_bfloat16 gVh[(size_t)NHtot * Tt * HD];
__device__ __align__(128) __nv_bfloat16 gVl[(size_t)NHtot * Tt * HD];

__device__ __forceinline__ uint32_t s2u(const void* p) {
  return (uint32_t)__cvta_generic_to_shared(p);
}
__device__ __forceinline__ void ldmx4(uint32_t* r, uint32_t a) {
  asm volatile("ldmatrix.sync.aligned.m8n8.x4.shared.b16 {%0,%1,%2,%3},[%4];"
               : "=r"(r[0]), "=r"(r[1]), "=r"(r[2]), "=r"(r[3]) : "r"(a));
}
__device__ __forceinline__ void ldmx4t(uint32_t* r, uint32_t a) {
  asm volatile("ldmatrix.sync.aligned.m8n8.x4.trans.shared.b16 {%0,%1,%2,%3},[%4];"
               : "=r"(r[0]), "=r"(r[1]), "=r"(r[2]), "=r"(r[3]) : "r"(a));
}
__device__ __forceinline__ void mmabf(float* c, const uint32_t* a, uint32_t b0, uint32_t b1) {
  asm volatile("mma.sync.aligned.m16n8k16.row.col.f32.bf16.bf16.f32 "
               "{%0,%1,%2,%3},{%4,%5,%6,%7},{%8,%9},{%0,%1,%2,%3};"
               : "+f"(c[0]), "+f"(c[1]), "+f"(c[2]), "+f"(c[3])
               : "r"(a[0]), "r"(a[1]), "r"(a[2]), "r"(a[3]), "r"(b0), "r"(b1));
}
__device__ __forceinline__ uint32_t pack2(float lo, float hi) {
  uint32_t r;
  asm("cvt.rn.bf16x2.f32 %0, %1, %2;" : "=r"(r) : "f"(hi), "f"(lo));
  return r;
}
__device__ __forceinline__ float bflo(uint32_t p) { return __uint_as_float(p << 16); }
__device__ __forceinline__ float bfhi(uint32_t p) { return __uint_as_float(p & 0xffff0000u); }
__device__ __forceinline__ void cpasync16(uint32_t saddr, const void* g) {
  asm volatile("cp.async.cg.shared.global [%0], [%1], 16;" :: "r"(saddr), "l"(g));
}
__device__ __forceinline__ void cp_commit() { asm volatile("cp.async.commit_group;"); }

// 64-token hi/lo tile -> swizzled stage (NT=256: 2x2 cp.async per thread)
__device__ __forceinline__ void issue_tile(const __nv_bfloat16* ph,
                                           const __nv_bfloat16* pl,
                                           uint32_t dst, int tid) {
#pragma unroll
  for (int i = 0; i < 2; i++) {
    int q = tid + i * NT;             // 0..511
    int r = q >> 3, c = q & 7;
    uint32_t off = r * 128 + ((c ^ (r & 7)) << 4);
    cpasync16(dst + off,         (const char*)ph + r * 128 + c * 16);
    cpasync16(dst + PLANE + off, (const char*)pl + r * 128 + c * 16);
  }
}
// 128-token Q tile
__device__ __forceinline__ void issue_q(const __nv_bfloat16* ph,
                                        const __nv_bfloat16* pl,
                                        uint32_t dst, int tid) {
#pragma unroll
  for (int i = 0; i < 4; i++) {
    int q = tid + i * NT;             // 0..1023
    int r = q >> 3, c = q & 7;
    uint32_t off = r * 128 + ((c ^ (r & 7)) << 4);
    cpasync16(dst + off,          (const char*)ph + r * 128 + c * 16);
    cpasync16(dst + QPLANE + off, (const char*)pl + r * 128 + c * 16);
  }
}

// QK: sacc += Q(smem)*K(stage)^T, 3-term bf16 split; Q frags loaded per chunk
__device__ __forceinline__ void qk_mma(float sacc[8][4], uint32_t Kst,
                                       uint32_t Qst, int lane, int warp) {
  const int ar   = (warp << 4) + (lane & 15);
  const int aSel = lane >> 4;
  const int x7a  = ar & 7;
  const int bTok = ((lane >> 4) << 3) + (lane & 7);
  const int bSel = (lane >> 3) & 1;
  const int x7   = lane & 7;
#pragma unroll
  for (int ch = 0; ch < 4; ch++) {
    uint32_t qh[4], ql[4];
    uint32_t aq = Qst + ar * 128 + (((2 * ch + aSel) ^ x7a) << 4);
    ldmx4(qh, aq);
    ldmx4(ql, aq + QPLANE);
#pragma unroll
    for (int p = 0; p < 4; p++) {
      uint32_t bh[4], bl[4];
      uint32_t a = Kst + (p * 16 + bTok) * 128 + (((2 * ch + bSel) ^ x7) << 4);
      ldmx4(bh, a);
      ldmx4(bl, a + PLANE);
      mmabf(sacc[2 * p],     qh, bh[0], bh[1]);
      mmabf(sacc[2 * p],     qh, bl[0], bl[1]);
      mmabf(sacc[2 * p],     ql, bh[0], bh[1]);
      mmabf(sacc[2 * p + 1], qh, bh[2], bh[3]);
      mmabf(sacc[2 * p + 1], qh, bl[2], bl[3]);
      mmabf(sacc[2 * p + 1], ql, bh[2], bh[3]);
    }
  }
}

// ---------------------------------------------------------------------------
// pre-pass: fp32 [n][t][e] -> per-head bf16 hi/lo planes [nh][t][d]
// ---------------------------------------------------------------------------
__global__ __launch_bounds__(256) void conv_kernel(
    const float* __restrict__ Q, const float* __restrict__ K,
    const float* __restrict__ V) {
  const float* src;
  __nv_bfloat16 *dh, *dl;
  if (blockIdx.y == 0)      { src = Q; dh = gQh; dl = gQl; }
  else if (blockIdx.y == 1) { src = K; dh = gKh; dl = gKl; }
  else                      { src = V; dh = gVh; dl = gVl; }
  size_t i = (size_t)blockIdx.x * 256 + threadIdx.x;
  float2 f = ((const float2*)src)[i];
  int e2 = (int)(i & 511);
  size_t tn = i >> 9;
  int e = e2 << 1, h = e >> 6, d = e & 63;
  int t = (int)(tn & 2047), n = (int)(tn >> 11);
  size_t o = ((((size_t)(n * 16 + h)) * Tt + t) * HD + d) >> 1;
  uint32_t hi = pack2(f.x, f.y);
  uint32_t lo = pack2(f.x - bflo(hi), f.y - bfhi(hi));
  ((uint32_t*)dh)[o] = hi;
  ((uint32_t*)dl)[o] = lo;
}

// ---------------------------------------------------------------------------
// fused attention: BM=128, 8 warps, 2 CTAs/SM
// ---------------------------------------------------------------------------
__global__ __launch_bounds__(NT, 2) void fused_attn_kernel(
    float* __restrict__ attn, float* __restrict__ Y) {
  extern __shared__ char smem[];
  const uint32_t sb = s2u(smem);
  const uint32_t Qst = sb + OFF_Q;
  const uint32_t S4[4] = {sb + OFF_S, sb + OFF_S + STAGE,
                          sb + OFF_S + 2 * STAGE, sb + OFF_S + 3 * STAGE};

  const int nh = blockIdx.y, n = nh >> 4;
  const int q0 = ((int)gridDim.x - 1 - (int)blockIdx.x) * BM;  // heavy-first
  const int tid = threadIdx.x, warp = tid >> 5, lane = tid & 31;
  const int ktl = (q0 >> 6) + 1;   // last k tile index (half-masked for low warps)

  const size_t hb = (size_t)nh * Tt * HD;
  const __nv_bfloat16 *Kh = gKh + hb, *Kl = gKl + hb;
  const __nv_bfloat16 *Vh = gVh + hb, *Vl = gVl + hb;

  // ---- prologue: Q tile into persistent smem ----
  issue_q(gQh + hb + (size_t)q0 * HD, gQl + hb + (size_t)q0 * HD, Qst, tid);
  cp_commit();

  const int rowA = q0 + (warp << 4) + (lane >> 2);
  const int cOff = 2 * (lane & 3);

  // ================= pass 1: row sums (4-stage K pipeline) =================
#pragma unroll
  for (int t = 0; t < 3; t++) {
    int tt = t <= ktl ? t : ktl;
    issue_tile(Kh + (size_t)tt * BN * HD, Kl + (size_t)tt * BN * HD, S4[t], tid);
    cp_commit();
  }
  float rs0 = 0.f, rs1 = 0.f;
  for (int kt = 0; kt <= ktl; kt++) {
    asm volatile("cp.async.wait_group 2;");
    __syncthreads();
    {
      int tt = kt + 3 <= ktl ? kt + 3 : ktl;
      issue_tile(Kh + (size_t)tt * BN * HD, Kl + (size_t)tt * BN * HD,
                 S4[(kt + 3) & 3], tid);
      cp_commit();
    }
    float sacc[8][4];
#pragma unroll
    for (int i = 0; i < 8; i++)
#pragma unroll
      for (int j = 0; j < 4; j++) sacc[i][j] = 0.f;
    qk_mma(sacc, S4[kt & 3], Qst, lane, warp);

    const int k0 = kt * BN;
    const bool msk = (k0 + BN - 1) > rowA;
#pragma unroll
    for (int nf = 0; nf < 8; nf++) {
      const int c = k0 + (nf << 3) + cOff;
      float e0 = __expf(sacc[nf][0] * SCALE);
      float e1 = __expf(sacc[nf][1] * SCALE);
      float e2 = __expf(sacc[nf][2] * SCALE);
      float e3 = __expf(sacc[nf][3] * SCALE);
      if (msk) {
        if (c     > rowA)     e0 = 0.f;
        if (c + 1 > rowA)     e1 = 0.f;
        if (c     > rowA + 8) e2 = 0.f;
        if (c + 1 > rowA + 8) e3 = 0.f;
      }
      rs0 += e0 + e1;
      rs1 += e2 + e3;
    }
  }
  rs0 += __shfl_xor_sync(0xffffffffu, rs0, 1);
  rs0 += __shfl_xor_sync(0xffffffffu, rs0, 2);
  rs1 += __shfl_xor_sync(0xffffffffu, rs1, 1);
  rs1 += __shfl_xor_sync(0xffffffffu, rs1, 2);
  const float inv0 = 1.f / rs0;
  const float inv1 = 1.f / rs1;

  // ================= pass 2: attn write + P@V (2x2 stages) =================
  __syncthreads();   // all pass-1 stage reads complete
  issue_tile(Kh, Kl, S4[0], tid);
  issue_tile(Vh, Vl, S4[2], tid);
  cp_commit();

  // zero-fill fully-masked columns [q0+128, Tt) (overlaps first loads)
  if (q0 + BM < Tt) {
    const int zs = q0 + BM;
    const int w4 = (Tt - zs) >> 2;
    const float4 z = make_float4(0.f, 0.f, 0.f, 0.f);
    float* base = attn + ((size_t)nh * Tt + q0) * Tt + zs;
    for (int r = 0; r < BM; r++) {
      float4* row = (float4*)(base + (size_t)r * Tt);
      for (int c = tid; c < w4; c += NT) row[c] = z;
    }
  }

  float yacc[8][4];
#pragma unroll
  for (int i = 0; i < 8; i++)
#pragma unroll
    for (int j = 0; j < 4; j++) yacc[i][j] = 0.f;

  const int vTok = (((lane >> 3) & 1) << 3) + (lane & 7);
  const int vSel = lane >> 4;
  const int x7 = lane & 7;
  float* pRowA = attn + ((size_t)nh * Tt + rowA) * Tt;
  float* pRowB = pRowA + (size_t)8 * Tt;

  for (int kt = 0; kt <= ktl; kt++) {
    asm volatile("cp.async.wait_group 0;");
    __syncthreads();
    if (kt < ktl) {
      issue_tile(Kh + (size_t)(kt + 1) * BN * HD, Kl + (size_t)(kt + 1) * BN * HD,
                 S4[(kt + 1) & 1], tid);
      issue_tile(Vh + (size_t)(kt + 1) * BN * HD, Vl + (size_t)(kt + 1) * BN * HD,
                 S4[2 + ((kt + 1) & 1)], tid);
      cp_commit();
    }
    const uint32_t Kst = S4[kt & 1];
    const uint32_t Vst = S4[2 + (kt & 1)];

    float sacc[8][4];
#pragma unroll
    for (int i = 0; i < 8; i++)
#pragma unroll
      for (int j = 0; j < 4; j++) sacc[i][j] = 0.f;
    qk_mma(sacc, Kst, Qst, lane, warp);

    const int k0 = kt * BN;
    const bool msk = (k0 + BN - 1) > rowA;
#pragma unroll
    for (int cc = 0; cc < 4; cc++) {
      float e[2][4];
#pragma unroll
      for (int s = 0; s < 2; s++) {
        const int nf = 2 * cc + s;
        const int c = k0 + (nf << 3) + cOff;
        e[s][0] = __expf(sacc[nf][0] * SCALE) * inv0;
        e[s][1] = __expf(sacc[nf][1] * SCALE) * inv0;
        e[s][2] = __expf(sacc[nf][2] * SCALE) * inv1;
        e[s][3] = __expf(sacc[nf][3] * SCALE) * inv1;
        if (msk) {
          if (c     > rowA)     e[s][0] = 0.f;
          if (c + 1 > rowA)     e[s][1] = 0.f;
          if (c     > rowA + 8) e[s][2] = 0.f;
          if (c + 1 > rowA + 8) e[s][3] = 0.f;
        }
        *(float2*)(pRowA + c) = make_float2(e[s][0], e[s][1]);
        *(float2*)(pRowB + c) = make_float2(e[s][2], e[s][3]);
      }
      // pack P fragments (C-layout == A-layout) and PV this k-chunk
      uint32_t ah[4], al[4];
      ah[0] = pack2(e[0][0], e[0][1]);
      ah[1] = pack2(e[0][2], e[0][3]);
      ah[2] = pack2(e[1][0], e[1][1]);
      ah[3] = pack2(e[1][2], e[1][3]);
      al[0] = pack2(e[0][0] - bflo(ah[0]), e[0][1] - bfhi(ah[0]));
      al[1] = pack2(e[0][2] - bflo(ah[1]), e[0][3] - bfhi(ah[1]));
      al[2] = pack2(e[1][0] - bflo(ah[2]), e[1][1] - bfhi(ah[2]));
      al[3] = pack2(e[1][2] - bflo(ah[3]), e[1][3] - bfhi(ah[3]));
#pragma unroll
      for (int p = 0; p < 4; p++) {
        uint32_t bh[4], bl[4];
        uint32_t a = Vst + (cc * 16 + vTok) * 128 + (((2 * p + vSel) ^ x7) << 4);
        ldmx4t(bh, a);
        ldmx4t(bl, a + PLANE);
        mmabf(yacc[2 * p],     ah, bh[0], bh[1]);
        mmabf(yacc[2 * p],     ah, bl[0], bl[1]);
        mmabf(yacc[2 * p],     al, bh[0], bh[1]);
        mmabf(yacc[2 * p + 1], ah, bh[2], bh[3]);
        mmabf(yacc[2 * p + 1], ah, bl[2], bl[3]);
        mmabf(yacc[2 * p + 1], al, bh[2], bh[3]);
      }
    }
  }

  // ---- y store ----
  const int h = nh & 15;
  float* y0 = Y + (size_t)(n * Tt + rowA) * Ee + h * HD;
  float* y1 = y0 + (size_t)8 * Ee;
#pragma unroll
  for (int nf = 0; nf < 8; nf++) {
    const int c = (nf << 3) + cOff;
    *(float2*)(y0 + c) = make_float2(yacc[nf][0], yacc[nf][1]);
    *(float2*)(y1 + c) = make_float2(yacc[nf][2], yacc[nf][3]);
  }
}

// ---------------------------------------------------------------------------
extern "C" void kernel_launch(void* const* d_in, const int* in_sizes, int n_in,
                              void* d_out, int out_size) {
  const float* q = (const float*)d_in[0];
  const float* k = (const float*)d_in[1];
  const float* v = (const float*)d_in[2];

  float* y    = (float*)d_out;
  float* attn = (float*)d_out + (size_t)4 * Tt * Ee;

  dim3 cg((unsigned)((size_t)4 * Tt * (Ee / 2) / 256), 3);
  conv_kernel<<<cg, 256>>>(q, k, v);

  cudaFuncSetAttribute(fused_attn_kernel,
                       cudaFuncAttributeMaxDynamicSharedMemorySize, SMEM_BYTES);
  dim3 grid(Tt / BM, NHtot);
  fused_attn_kernel<<<grid, NT, SMEM_BYTES>>>(attn, y);
}

// round 7
// speedup vs baseline: 1.1290x; 1.1290x over previous
#include <cuda_runtime.h>
#include <cuda_bf16.h>
#include <cstdint>

namespace {
constexpr int Tt  = 2048;
constexpr int Ee  = 1024;
constexpr int HD  = 64;
constexpr int BM  = 64;
constexpr int BN  = 64;
constexpr int NT  = 128;            // 4 warps
constexpr int NHtot = 64;
constexpr float SCALE = 0.125f;
constexpr int PLANE = 8192;         // 64-token plane (128B rows, swizzled)
constexpr int STAGE = 2 * PLANE;    // hi+lo stage (16 KB)
constexpr int SMEM_BYTES = 3 * STAGE;  // 49152 -> 4 CTAs/SM
}

// preconverted per-head bf16 hi/lo planes: [nh][t][d]
__device__ __align__(128) __nv_bfloat16 gQh[(size_t)NHtot * Tt * HD];
__device__ __align__(128) __nv_bfloat16 gQl[(size_t)NHtot * Tt * HD];
__device__ __align__(128) __nv_bfloat16 gKh[(size_t)NHtot * Tt * HD];
__device__ __align__(128) __nv_bfloat16 gKl[(size_t)NHtot * Tt * HD];
__device__ __align__(128) __nv_bfloat16 gVh[(size_t)NHtot * Tt * HD];
__device__ __align__(128) __nv_bfloat16 gVl[(size_t)NHtot * Tt * HD];

__device__ __forceinline__ uint32_t s2u(const void* p) {
  return (uint32_t)__cvta_generic_to_shared(p);
}
__device__ __forceinline__ void ldmx4(uint32_t* r, uint32_t a) {
  asm volatile("ldmatrix.sync.aligned.m8n8.x4.shared.b16 {%0,%1,%2,%3},[%4];"
               : "=r"(r[0]), "=r"(r[1]), "=r"(r[2]), "=r"(r[3]) : "r"(a));
}
__device__ __forceinline__ void ldmx4t(uint32_t* r, uint32_t a) {
  asm volatile("ldmatrix.sync.aligned.m8n8.x4.trans.shared.b16 {%0,%1,%2,%3},[%4];"
               : "=r"(r[0]), "=r"(r[1]), "=r"(r[2]), "=r"(r[3]) : "r"(a));
}
__device__ __forceinline__ void mmabf(float* c, const uint32_t* a, uint32_t b0, uint32_t b1) {
  asm volatile("mma.sync.aligned.m16n8k16.row.col.f32.bf16.bf16.f32 "
               "{%0,%1,%2,%3},{%4,%5,%6,%7},{%8,%9},{%0,%1,%2,%3};"
               : "+f"(c[0]), "+f"(c[1]), "+f"(c[2]), "+f"(c[3])
               : "r"(a[0]), "r"(a[1]), "r"(a[2]), "r"(a[3]), "r"(b0), "r"(b1));
}
__device__ __forceinline__ uint32_t pack2(float lo, float hi) {
  uint32_t r;
  asm("cvt.rn.bf16x2.f32 %0, %1, %2;" : "=r"(r) : "f"(hi), "f"(lo));
  return r;
}
__device__ __forceinline__ float bflo(uint32_t p) { return __uint_as_float(p << 16); }
__device__ __forceinline__ float bfhi(uint32_t p) { return __uint_as_float(p & 0xffff0000u); }
__device__ __forceinline__ void cpasync16(uint32_t saddr, const void* g) {
  asm volatile("cp.async.cg.shared.global [%0], [%1], 16;" :: "r"(saddr), "l"(g));
}
__device__ __forceinline__ void cp_commit() { asm volatile("cp.async.commit_group;"); }

// 64-token hi/lo tile -> swizzled smem stage (8 cp.async per thread at NT=128)
__device__ __forceinline__ void issue_tile(const __nv_bfloat16* ph,
                                           const __nv_bfloat16* pl,
                                           uint32_t dst, int tid) {
#pragma unroll
  for (int i = 0; i < 4; i++) {
    int q = tid + i * NT;             // 0..511
    int r = q >> 3, c = q & 7;
    uint32_t off = r * 128 + ((c ^ (r & 7)) << 4);
    cpasync16(dst + off,         (const char*)ph + r * 128 + c * 16);
    cpasync16(dst + PLANE + off, (const char*)pl + r * 128 + c * 16);
  }
}

// QK for one 32-col half (p0 = 0 or 2): sacc[4][4] covers n = p0*16 .. p0*16+31
__device__ __forceinline__ void qk_half(float sacc[4][4], uint32_t Kst,
                                        const uint32_t qah[4][4],
                                        const uint32_t qal[4][4],
                                        int lane, int p0) {
  const int bTok = ((lane >> 4) << 3) + (lane & 7);
  const int bSel = (lane >> 3) & 1;
  const int x7 = lane & 7;
#pragma unroll
  for (int ch = 0; ch < 4; ch++) {
#pragma unroll
    for (int pp = 0; pp < 2; pp++) {
      uint32_t bh[4], bl[4];
      uint32_t a = Kst + ((p0 + pp) * 16 + bTok) * 128 + (((2 * ch + bSel) ^ x7) << 4);
      ldmx4(bh, a);
      ldmx4(bl, a + PLANE);
      mmabf(sacc[2 * pp],     qah[ch], bh[0], bh[1]);
      mmabf(sacc[2 * pp],     qah[ch], bl[0], bl[1]);
      mmabf(sacc[2 * pp],     qal[ch], bh[0], bh[1]);
      mmabf(sacc[2 * pp + 1], qah[ch], bh[2], bh[3]);
      mmabf(sacc[2 * pp + 1], qah[ch], bl[2], bl[3]);
      mmabf(sacc[2 * pp + 1], qal[ch], bh[2], bh[3]);
    }
  }
}

// ---------------------------------------------------------------------------
// pre-pass: fp32 [n][t][e] -> per-head bf16 hi/lo planes [nh][t][d]
// ---------------------------------------------------------------------------
__global__ __launch_bounds__(256) void conv_kernel(
    const float* __restrict__ Q, const float* __restrict__ K,
    const float* __restrict__ V) {
  const float* src;
  __nv_bfloat16 *dh, *dl;
  if (blockIdx.y == 0)      { src = Q; dh = gQh; dl = gQl; }
  else if (blockIdx.y == 1) { src = K; dh = gKh; dl = gKl; }
  else                      { src = V; dh = gVh; dl = gVl; }
  size_t i = (size_t)blockIdx.x * 256 + threadIdx.x;
  float2 f = ((const float2*)src)[i];
  int e2 = (int)(i & 511);
  size_t tn = i >> 9;
  int e = e2 << 1, h = e >> 6, d = e & 63;
  int t = (int)(tn & 2047), n = (int)(tn >> 11);
  size_t o = ((((size_t)(n * 16 + h)) * Tt + t) * HD + d) >> 1;
  uint32_t hi = pack2(f.x, f.y);
  uint32_t lo = pack2(f.x - bflo(hi), f.y - bfhi(hi));
  ((uint32_t*)dh)[o] = hi;
  ((uint32_t*)dl)[o] = lo;
}

// ---------------------------------------------------------------------------
// fused attention: BM=64, 4 warps, 4 CTAs/SM, 3x16KB stages
// ---------------------------------------------------------------------------
__global__ __launch_bounds__(NT, 4) void fused_attn_kernel(
    float* __restrict__ attn, float* __restrict__ Y) {
  extern __shared__ char smem[];
  const uint32_t sb = s2u(smem);
  const uint32_t S[3] = {sb, sb + STAGE, sb + 2 * STAGE};

  const int nh = blockIdx.y, n = nh >> 4;
  const int q0 = ((int)gridDim.x - 1 - (int)blockIdx.x) * BM;  // heavy-first
  const int tid = threadIdx.x, warp = tid >> 5, lane = tid & 31;
  const int ktl = q0 >> 6;

  const size_t hb = (size_t)nh * Tt * HD;
  const __nv_bfloat16 *Kh = gKh + hb, *Kl = gKl + hb;
  const __nv_bfloat16 *Vh = gVh + hb, *Vl = gVl + hb;

  // ---- prologue: Q -> S2, K0 -> S0, K1 -> S1 ----
  issue_tile(gQh + hb + (size_t)q0 * HD, gQl + hb + (size_t)q0 * HD, S[2], tid);
  cp_commit();
  issue_tile(Kh, Kl, S[0], tid);
  cp_commit();
  {
    int t1 = ktl >= 1 ? 1 : 0;
    issue_tile(Kh + (size_t)t1 * BN * HD, Kl + (size_t)t1 * BN * HD, S[1], tid);
    cp_commit();
  }
  asm volatile("cp.async.wait_group 2;");   // own Q group done
  __syncthreads();                          // ALL threads' Q copies visible
  uint32_t qah[4][4], qal[4][4];
  {
    const int ar = (warp << 4) + (lane & 15);
    const int aSel = lane >> 4;
    const int x7a = ar & 7;
#pragma unroll
    for (int ch = 0; ch < 4; ch++) {
      uint32_t a = S[2] + ar * 128 + (((2 * ch + aSel) ^ x7a) << 4);
      ldmx4(qah[ch], a);
      ldmx4(qal[ch], a + PLANE);
    }
  }

  const int rowA = q0 + (warp << 4) + (lane >> 2);
  const int cOff = 2 * (lane & 3);

  // ================= pass 1: row sums (3-stage K pipeline) =================
  float rs0 = 0.f, rs1 = 0.f;
  for (int kt = 0; kt <= ktl; kt++) {
    asm volatile("cp.async.wait_group 1;");   // K_kt (all but newest group)
    __syncthreads();                           // cross-thread visibility
    {
      int tt = kt + 2 <= ktl ? kt + 2 : ktl;
      issue_tile(Kh + (size_t)tt * BN * HD, Kl + (size_t)tt * BN * HD,
                 S[(kt + 2) % 3], tid);
      cp_commit();
    }
    const uint32_t Kst = S[kt % 3];
    const int k0 = kt * BN;
    const bool msk = (k0 + BN - 1) > rowA;
#pragma unroll
    for (int hh = 0; hh < 2; hh++) {
      float sacc[4][4];
#pragma unroll
      for (int i = 0; i < 4; i++)
#pragma unroll
        for (int j = 0; j < 4; j++) sacc[i][j] = 0.f;
      qk_half(sacc, Kst, qah, qal, lane, 2 * hh);
#pragma unroll
      for (int nfl = 0; nfl < 4; nfl++) {
        const int c = k0 + ((4 * hh + nfl) << 3) + cOff;
        float e0 = __expf(sacc[nfl][0] * SCALE);
        float e1 = __expf(sacc[nfl][1] * SCALE);
        float e2 = __expf(sacc[nfl][2] * SCALE);
        float e3 = __expf(sacc[nfl][3] * SCALE);
        if (msk) {
          if (c     > rowA)     e0 = 0.f;
          if (c + 1 > rowA)     e1 = 0.f;
          if (c     > rowA + 8) e2 = 0.f;
          if (c + 1 > rowA + 8) e3 = 0.f;
        }
        rs0 += e0 + e1;
        rs1 += e2 + e3;
      }
    }
  }
  rs0 += __shfl_xor_sync(0xffffffffu, rs0, 1);
  rs0 += __shfl_xor_sync(0xffffffffu, rs0, 2);
  rs1 += __shfl_xor_sync(0xffffffffu, rs1, 1);
  rs1 += __shfl_xor_sync(0xffffffffu, rs1, 2);
  const float inv0 = 1.f / rs0;
  const float inv1 = 1.f / rs1;

  // ================= pass 2: attn write + P@V =================
  asm volatile("cp.async.wait_group 0;");
  __syncthreads();                     // pass-1 stage reads complete everywhere
  issue_tile(Kh, Kl, S[0], tid);       // K double-buffer: S0/S1
  cp_commit();
  issue_tile(Vh, Vl, S[2], tid);       // V single-buffer: S2
  cp_commit();

  // zero-fill fully-masked columns [q0+64, Tt) (overlaps first loads)
  if (q0 + BM < Tt) {
    const int zs = q0 + BM;
    const int w4 = (Tt - zs) >> 2;
    const float4 z = make_float4(0.f, 0.f, 0.f, 0.f);
    float* base = attn + ((size_t)nh * Tt + q0) * Tt + zs;
    for (int r = 0; r < BM; r++) {
      float4* row = (float4*)(base + (size_t)r * Tt);
      for (int c = tid; c < w4; c += NT) row[c] = z;
    }
  }

  float yacc[8][4];
#pragma unroll
  for (int i = 0; i < 8; i++)
#pragma unroll
    for (int j = 0; j < 4; j++) yacc[i][j] = 0.f;

  const int vTok = (((lane >> 3) & 1) << 3) + (lane & 7);
  const int vSel = lane >> 4;
  const int x7 = lane & 7;
  float* pRowA = attn + ((size_t)nh * Tt + rowA) * Tt;
  float* pRowB = pRowA + (size_t)8 * Tt;

  for (int kt = 0; kt <= ktl; kt++) {
    asm volatile("cp.async.wait_group 1;");   // K_kt (V_kt may still fly)
    __syncthreads();
    {
      int tt = kt + 1 <= ktl ? kt + 1 : ktl;
      issue_tile(Kh + (size_t)tt * BN * HD, Kl + (size_t)tt * BN * HD,
                 S[(kt + 1) & 1], tid);
      cp_commit();
    }
    const uint32_t Kst = S[kt & 1];
    const int k0 = kt * BN;
    const bool msk = (k0 + BN - 1) > rowA;

#pragma unroll
    for (int hh = 0; hh < 2; hh++) {
      const int p0 = 2 * hh;
      float sacc[4][4];
#pragma unroll
      for (int i = 0; i < 4; i++)
#pragma unroll
        for (int j = 0; j < 4; j++) sacc[i][j] = 0.f;
      qk_half(sacc, Kst, qah, qal, lane, p0);

      // exp + normalize + mask + store attn; pack P fragments per k16 chunk
      uint32_t pk[2][8];   // [pp][ah0..3, al0..3]
#pragma unroll
      for (int pp = 0; pp < 2; pp++) {
        float e[2][4];
#pragma unroll
        for (int s = 0; s < 2; s++) {
          const int nfl = 2 * pp + s;
          const int c = k0 + ((2 * (p0 + pp) + s) << 3) + cOff;
          e[s][0] = __expf(sacc[nfl][0] * SCALE) * inv0;
          e[s][1] = __expf(sacc[nfl][1] * SCALE) * inv0;
          e[s][2] = __expf(sacc[nfl][2] * SCALE) * inv1;
          e[s][3] = __expf(sacc[nfl][3] * SCALE) * inv1;
          if (msk) {
            if (c     > rowA)     e[s][0] = 0.f;
            if (c + 1 > rowA)     e[s][1] = 0.f;
            if (c     > rowA + 8) e[s][2] = 0.f;
            if (c + 1 > rowA + 8) e[s][3] = 0.f;
          }
          *(float2*)(pRowA + c) = make_float2(e[s][0], e[s][1]);
          *(float2*)(pRowB + c) = make_float2(e[s][2], e[s][3]);
        }
        pk[pp][0] = pack2(e[0][0], e[0][1]);
        pk[pp][1] = pack2(e[0][2], e[0][3]);
        pk[pp][2] = pack2(e[1][0], e[1][1]);
        pk[pp][3] = pack2(e[1][2], e[1][3]);
        pk[pp][4] = pack2(e[0][0] - bflo(pk[pp][0]), e[0][1] - bfhi(pk[pp][0]));
        pk[pp][5] = pack2(e[0][2] - bflo(pk[pp][1]), e[0][3] - bfhi(pk[pp][1]));
        pk[pp][6] = pack2(e[1][0] - bflo(pk[pp][2]), e[1][1] - bfhi(pk[pp][2]));
        pk[pp][7] = pack2(e[1][2] - bflo(pk[pp][3]), e[1][3] - bfhi(pk[pp][3]));
      }

      if (hh == 0) {
        asm volatile("cp.async.wait_group 1;");   // V_kt done (newest = K_{kt+1})
        __syncthreads();                           // cross-thread visibility
      }

      // PV for this half: k-chunks cc = p0, p0+1 from V stage S2
#pragma unroll
      for (int pp = 0; pp < 2; pp++) {
        const int cc = p0 + pp;
        const uint32_t* ah = &pk[pp][0];
        const uint32_t* al = &pk[pp][4];
#pragma unroll
        for (int p = 0; p < 4; p++) {
          uint32_t bh[4], bl[4];
          uint32_t a = S[2] + (cc * 16 + vTok) * 128 + (((2 * p + vSel) ^ x7) << 4);
          ldmx4t(bh, a);
          ldmx4t(bl, a + PLANE);
          mmabf(yacc[2 * p],     ah, bh[0], bh[1]);
          mmabf(yacc[2 * p],     ah, bl[0], bl[1]);
          mmabf(yacc[2 * p],     al, bh[0], bh[1]);
          mmabf(yacc[2 * p + 1], ah, bh[2], bh[3]);
          mmabf(yacc[2 * p + 1], ah, bl[2], bl[3]);
          mmabf(yacc[2 * p + 1], al, bh[2], bh[3]);
        }
      }
    }

    __syncthreads();                   // all warps done reading V_kt
    {
      int tt = kt + 1 <= ktl ? kt + 1 : ktl;
      issue_tile(Vh + (size_t)tt * BN * HD, Vl + (size_t)tt * BN * HD, S[2], tid);
      cp_commit();
    }
  }

  // ---- y store ----
  const int h = nh & 15;
  float* y0 = Y + (size_t)(n * Tt + rowA) * Ee + h * HD;
  float* y1 = y0 + (size_t)8 * Ee;
#pragma unroll
  for (int nf = 0; nf < 8; nf++) {
    const int c = (nf << 3) + cOff;
    *(float2*)(y0 + c) = make_float2(yacc[nf][0], yacc[nf][1]);
    *(float2*)(y1 + c) = make_float2(yacc[nf][2], yacc[nf][3]);
  }
}

// ---------------------------------------------------------------------------
extern "C" void kernel_launch(void* const* d_in, const int* in_sizes, int n_in,
                              void* d_out, int out_size) {
  const float* q = (const float*)d_in[0];
  const float* k = (const float*)d_in[1];
  const float* v = (const float*)d_in[2];

  float* y    = (float*)d_out;
  float* attn = (float*)d_out + (size_t)4 * Tt * Ee;

  dim3 cg((unsigned)((size_t)4 * Tt * (Ee / 2) / 256), 3);
  conv_kernel<<<cg, 256>>>(q, k, v);

  cudaFuncSetAttribute(fused_attn_kernel,
                       cudaFuncAttributeMaxDynamicSharedMemorySize, SMEM_BYTES);
  dim3 grid(Tt / BM, NHtot);
  fused_attn_kernel<<<grid, NT, SMEM_BYTES>>>(attn, y);
}

// round 9
// speedup vs baseline: 1.8133x; 1.6061x over previous
#include <cuda_runtime.h>
#include <cuda_fp16.h>
#include <cstdint>

namespace {
constexpr int Tt = 2048, Ee = 1024, HD = 64;
constexpr int BM = 64, BN = 64;
constexpr int NT = 128;             // 4 warps
constexpr int NHtot = 64;
constexpr float SCALE = 0.125f;
constexpr int PLANE = 8192;         // 64 tokens x 128B (fp16, SW-pattern)
// smem: SK[3] | SV[3]  (Q staged through SV[0] in prologue)
constexpr int SMEM_BYTES = 6 * PLANE;   // 49152 -> 4 CTAs/SM
}

// preconverted per-head fp16 planes [nh][t][d]
__device__ __align__(128) __half gQ[(size_t)NHtot * Tt * HD];
__device__ __align__(128) __half gK[(size_t)NHtot * Tt * HD];
__device__ __align__(128) __half gV[(size_t)NHtot * Tt * HD];

__device__ __forceinline__ uint32_t s2u(const void* p) {
  return (uint32_t)__cvta_generic_to_shared(p);
}
__device__ __forceinline__ void ldmx4(uint32_t* r, uint32_t a) {
  asm volatile("ldmatrix.sync.aligned.m8n8.x4.shared.b16 {%0,%1,%2,%3},[%4];"
               : "=r"(r[0]), "=r"(r[1]), "=r"(r[2]), "=r"(r[3]) : "r"(a));
}
__device__ __forceinline__ void ldmx4t(uint32_t* r, uint32_t a) {
  asm volatile("ldmatrix.sync.aligned.m8n8.x4.trans.shared.b16 {%0,%1,%2,%3},[%4];"
               : "=r"(r[0]), "=r"(r[1]), "=r"(r[2]), "=r"(r[3]) : "r"(a));
}
__device__ __forceinline__ void mmah(float* c, const uint32_t* a, uint32_t b0, uint32_t b1) {
  asm volatile("mma.sync.aligned.m16n8k16.row.col.f32.f16.f16.f32 "
               "{%0,%1,%2,%3},{%4,%5,%6,%7},{%8,%9},{%0,%1,%2,%3};"
               : "+f"(c[0]), "+f"(c[1]), "+f"(c[2]), "+f"(c[3])
               : "r"(a[0]), "r"(a[1]), "r"(a[2]), "r"(a[3]), "r"(b0), "r"(b1));
}
__device__ __forceinline__ uint32_t packh2(float lo, float hi) {
  __half2 h = __floats2half2_rn(lo, hi);   // .x = lo half
  return *reinterpret_cast<uint32_t*>(&h);
}
__device__ __forceinline__ void cpasync16(uint32_t saddr, const void* g) {
  asm volatile("cp.async.cg.shared.global [%0], [%1], 16;" :: "r"(saddr), "l"(g));
}
__device__ __forceinline__ void cp_commit() { asm volatile("cp.async.commit_group;"); }

// 64-token fp16 tile (64x128B) -> swizzled smem stage (4 cp.async/thread)
__device__ __forceinline__ void issue_tile(const __half* p, uint32_t dst, int tid) {
#pragma unroll
  for (int i = 0; i < 4; i++) {
    int q = tid + i * NT;             // 0..511
    int r = q >> 3, c = q & 7;
    uint32_t off = r * 128 + ((c ^ (r & 7)) << 4);
    cpasync16(dst + off, (const char*)p + r * 128 + c * 16);
  }
}

// full 64-wide QK tile: sacc[8][4] += Q(frag) * K(stage)^T, single fp16
__device__ __forceinline__ void qk_tile(float sacc[8][4], uint32_t Kst,
                                        const uint32_t qa[4][4], int lane) {
  const int bTok = ((lane >> 4) << 3) + (lane & 7);
  const int bSel = (lane >> 3) & 1;
  const int x7 = lane & 7;
#pragma unroll
  for (int ch = 0; ch < 4; ch++) {
#pragma unroll
    for (int p = 0; p < 4; p++) {
      uint32_t b[4];
      ldmx4(b, Kst + (p * 16 + bTok) * 128 + (((2 * ch + bSel) ^ x7) << 4));
      mmah(sacc[2 * p],     qa[ch], b[0], b[1]);
      mmah(sacc[2 * p + 1], qa[ch], b[2], b[3]);
    }
  }
}

// ---------------------------------------------------------------------------
// prepass: fp32 [n][t][e] -> per-head fp16 planes [nh][t][d]
// ---------------------------------------------------------------------------
__global__ __launch_bounds__(256) void conv_kernel(
    const float* __restrict__ Q, const float* __restrict__ K,
    const float* __restrict__ V) {
  const float* src;
  __half* dst;
  if (blockIdx.y == 0)      { src = Q; dst = gQ; }
  else if (blockIdx.y == 1) { src = K; dst = gK; }
  else                      { src = V; dst = gV; }
  size_t i = (size_t)blockIdx.x * 256 + threadIdx.x;   // float2 elements
  float2 f = ((const float2*)src)[i];
  int e2 = (int)(i & 511);
  size_t tn = i >> 9;
  int e = e2 << 1, h = e >> 6, d = e & 63;
  int t = (int)(tn & 2047), n = (int)(tn >> 11);
  size_t o = ((((size_t)(n * 16 + h)) * Tt + t) * HD + d) >> 1;
  ((uint32_t*)dst)[o] = packh2(f.x, f.y);
}

// ---------------------------------------------------------------------------
// fused attention: single-fp16 tensor ops, fp32 softmax path
// ---------------------------------------------------------------------------
__global__ __launch_bounds__(NT, 4) void fused_attn_kernel(
    float* __restrict__ attn, float* __restrict__ Y) {
  extern __shared__ char smem[];
  const uint32_t sb = s2u(smem);
  const uint32_t SK[3] = {sb, sb + PLANE, sb + 2 * PLANE};
  const uint32_t SV[3] = {sb + 3 * PLANE, sb + 4 * PLANE, sb + 5 * PLANE};

  const int nh = blockIdx.y, n = nh >> 4;
  const int q0 = ((int)gridDim.x - 1 - (int)blockIdx.x) * BM;  // heavy-first
  const int tid = threadIdx.x, warp = tid >> 5, lane = tid & 31;
  const int ktl = q0 >> 6;

  const size_t hb = (size_t)nh * Tt * HD;
  const __half* Kp = gK + hb;
  const __half* Vp = gV + hb;

  // ---- prologue: Q -> SV0; K0 -> SK0; K1 -> SK1 ----
  issue_tile(gQ + hb + (size_t)q0 * HD, SV[0], tid);
  cp_commit();
  issue_tile(Kp, SK[0], tid);
  cp_commit();
  {
    int t1 = ktl >= 1 ? 1 : 0;
    issue_tile(Kp + (size_t)t1 * BN * HD, SK[1], tid);
    cp_commit();
  }
  asm volatile("cp.async.wait_group 2;");   // Q landed (own groups)
  __syncthreads();                          // cross-thread visibility
  uint32_t qa[4][4];
  {
    const int ar = (warp << 4) + (lane & 15);
    const int aSel = lane >> 4;
    const int x7a = ar & 7;
#pragma unroll
    for (int ch = 0; ch < 4; ch++)
      ldmx4(qa[ch], SV[0] + ar * 128 + (((2 * ch + aSel) ^ x7a) << 4));
  }

  const int rowA = q0 + (warp << 4) + (lane >> 2);
  const int cOff = 2 * (lane & 3);

  // ================= pass 1: row sums (3-stage K pipeline) =================
  float rs0 = 0.f, rs1 = 0.f;
  for (int t = 0; t <= ktl; t++) {
    asm volatile("cp.async.wait_group 1;");   // K_t done (K_{t+1} may fly)
    __syncthreads();
    {
      int tt = t + 2 <= ktl ? t + 2 : ktl;
      issue_tile(Kp + (size_t)tt * BN * HD, SK[(t + 2) % 3], tid);
      cp_commit();
    }
    float sacc[8][4];
#pragma unroll
    for (int i = 0; i < 8; i++)
#pragma unroll
      for (int j = 0; j < 4; j++) sacc[i][j] = 0.f;
    qk_tile(sacc, SK[t % 3], qa, lane);

    const int k0 = t * BN;
    const bool msk = (k0 + BN - 1) > rowA;
#pragma unroll
    for (int nf = 0; nf < 8; nf++) {
      const int c = k0 + (nf << 3) + cOff;
      float e0 = __expf(sacc[nf][0] * SCALE);
      float e1 = __expf(sacc[nf][1] * SCALE);
      float e2 = __expf(sacc[nf][2] * SCALE);
      float e3 = __expf(sacc[nf][3] * SCALE);
      if (msk) {
        if (c     > rowA)     e0 = 0.f;
        if (c + 1 > rowA)     e1 = 0.f;
        if (c     > rowA + 8) e2 = 0.f;
        if (c + 1 > rowA + 8) e3 = 0.f;
      }
      rs0 += e0 + e1;
      rs1 += e2 + e3;
    }
  }
  rs0 += __shfl_xor_sync(0xffffffffu, rs0, 1);
  rs0 += __shfl_xor_sync(0xffffffffu, rs0, 2);
  rs1 += __shfl_xor_sync(0xffffffffu, rs1, 1);
  rs1 += __shfl_xor_sync(0xffffffffu, rs1, 2);
  const float inv0 = 1.f / rs0;
  const float inv1 = 1.f / rs1;

  // ================= pass 2: attn write + P@V (3x(K,V) stages) =============
  asm volatile("cp.async.wait_group 0;");
  __syncthreads();                     // pipeline drained; pass-1 reads done
  issue_tile(Kp, SK[0], tid);
  issue_tile(Vp, SV[0], tid);
  cp_commit();                         // pair 0
  {
    int t1 = ktl >= 1 ? 1 : 0;
    issue_tile(Kp + (size_t)t1 * BN * HD, SK[1], tid);
    issue_tile(Vp + (size_t)t1 * BN * HD, SV[1], tid);
    cp_commit();                       // pair 1
  }

  // zero-fill fully-masked columns [q0+64, Tt) (overlaps first loads)
  if (q0 + BM < Tt) {
    const int zs = q0 + BM;
    const int w4 = (Tt - zs) >> 2;
    const float4 z = make_float4(0.f, 0.f, 0.f, 0.f);
    float* base = attn + ((size_t)nh * Tt + q0) * Tt + zs;
    for (int r = 0; r < BM; r++) {
      float4* row = (float4*)(base + (size_t)r * Tt);
      for (int c = tid; c < w4; c += NT) row[c] = z;
    }
  }

  float yacc[8][4];
#pragma unroll
  for (int i = 0; i < 8; i++)
#pragma unroll
    for (int j = 0; j < 4; j++) yacc[i][j] = 0.f;

  const int vTok = (((lane >> 3) & 1) << 3) + (lane & 7);
  const int vSel = lane >> 4;
  const int x7 = lane & 7;
  float* pRowA = attn + ((size_t)nh * Tt + rowA) * Tt;
  float* pRowB = pRowA + (size_t)8 * Tt;

  for (int t = 0; t <= ktl; t++) {
    asm volatile("cp.async.wait_group 1;");   // pair_t done (pair_{t+1} flying)
    __syncthreads();
    {
      int tt = t + 2 <= ktl ? t + 2 : ktl;
      issue_tile(Kp + (size_t)tt * BN * HD, SK[(t + 2) % 3], tid);
      issue_tile(Vp + (size_t)tt * BN * HD, SV[(t + 2) % 3], tid);
      cp_commit();
    }
    float sacc[8][4];
#pragma unroll
    for (int i = 0; i < 8; i++)
#pragma unroll
      for (int j = 0; j < 4; j++) sacc[i][j] = 0.f;
    qk_tile(sacc, SK[t % 3], qa, lane);

    const uint32_t Vst = SV[t % 3];
    const int k0 = t * BN;
    const bool msk = (k0 + BN - 1) > rowA;

#pragma unroll
    for (int cc = 0; cc < 4; cc++) {
      // exp + normalize + mask + store attn for frags 2cc, 2cc+1
      float e[2][4];
#pragma unroll
      for (int s = 0; s < 2; s++) {
        const int nf = 2 * cc + s;
        const int c = k0 + (nf << 3) + cOff;
        e[s][0] = __expf(sacc[nf][0] * SCALE) * inv0;
        e[s][1] = __expf(sacc[nf][1] * SCALE) * inv0;
        e[s][2] = __expf(sacc[nf][2] * SCALE) * inv1;
        e[s][3] = __expf(sacc[nf][3] * SCALE) * inv1;
        if (msk) {
          if (c     > rowA)     e[s][0] = 0.f;
          if (c + 1 > rowA)     e[s][1] = 0.f;
          if (c     > rowA + 8) e[s][2] = 0.f;
          if (c + 1 > rowA + 8) e[s][3] = 0.f;
        }
        *(float2*)(pRowA + c) = make_float2(e[s][0], e[s][1]);
        *(float2*)(pRowB + c) = make_float2(e[s][2], e[s][3]);
      }
      // pack P (C-layout == A-layout) and PV this 16-wide k-chunk
      uint32_t a[4];
      a[0] = packh2(e[0][0], e[0][1]);
      a[1] = packh2(e[0][2], e[0][3]);
      a[2] = packh2(e[1][0], e[1][1]);
      a[3] = packh2(e[1][2], e[1][3]);
#pragma unroll
      for (int p = 0; p < 4; p++) {
        uint32_t b[4];
        ldmx4t(b, Vst + (cc * 16 + vTok) * 128 + (((2 * p + vSel) ^ x7) << 4));
        mmah(yacc[2 * p],     a, b[0], b[1]);
        mmah(yacc[2 * p + 1], a, b[2], b[3]);
      }
    }
  }

  // ---- y store ----
  const int h = nh & 15;
  float* y0 = Y + (size_t)(n * Tt + rowA) * Ee + h * HD;
  float* y1 = y0 + (size_t)8 * Ee;
#pragma unroll
  for (int nf = 0; nf < 8; nf++) {
    const int c = (nf << 3) + cOff;
    *(float2*)(y0 + c) = make_float2(yacc[nf][0], yacc[nf][1]);
    *(float2*)(y1 + c) = make_float2(yacc[nf][2], yacc[nf][3]);
  }
}

// ---------------------------------------------------------------------------
extern "C" void kernel_launch(void* const* d_in, const int* in_sizes, int n_in,
                              void* d_out, int out_size) {
  const float* q = (const float*)d_in[0];
  const float* k = (const float*)d_in[1];
  const float* v = (const float*)d_in[2];

  float* y    = (float*)d_out;
  float* attn = (float*)d_out + (size_t)4 * Tt * Ee;

  dim3 cg((unsigned)((size_t)4 * Tt * (Ee / 2) / 256), 3);
  conv_kernel<<<cg, 256>>>(q, k, v);

  cudaFuncSetAttribute(fused_attn_kernel,
                       cudaFuncAttributeMaxDynamicSharedMemorySize, SMEM_BYTES);
  dim3 grid(Tt / BM, NHtot);
  fused_attn_kernel<<<grid, NT, SMEM_BYTES>>>(attn, y);
}